// round 4
// baseline (speedup 1.0000x reference)
#include <cuda_runtime.h>

#define N_NODES 100000
#define N_EDGES 1600000
#define D 128
#define H 8
#define DH 16
#define DFF 256
#define CAP 96          // max in-degree capacity (Poisson mean 16; P(>96) ~ 0)

// ---------------- scratch (device globals; no allocation allowed) ----------
__device__ float g_Q[N_NODES * D];
__device__ float g_KV[(long)N_NODES * 2 * D];   // [node][K 0..127 | V 128..255]
__device__ float g_wV[N_NODES * D];
__device__ float g_z[N_NODES * H];
__device__ int   g_cnt[N_NODES];
__device__ int   g_csr[(long)N_NODES * CAP];

// k-pair interleaved weights: Wi[k2*C + c] = (W[2k2][c], W[2k2+1][c])
__device__ float2 g_Wqi[64 * D];
__device__ float2 g_Wki[64 * D];
__device__ float2 g_Wvi[64 * D];
__device__ float2 g_Woi[64 * D];
__device__ float2 g_W1i[64 * DFF];
__device__ float2 g_W2i[128 * D];

// ---------------- packed f32x2 helpers -------------------------------------
typedef unsigned long long u64;

__device__ __forceinline__ u64 ffma2(u64 a, u64 b, u64 c) {
    u64 d;
    asm("fma.rn.f32x2 %0, %1, %2, %3;" : "=l"(d) : "l"(a), "l"(b), "l"(c));
    return d;
}
union U2 { u64 p; float2 f; };
__device__ __forceinline__ float hsum2(u64 a) { U2 u; u.p = a; return u.f.x + u.f.y; }

// ---------------- interleave weights (runs every call; ~5us) ---------------
__global__ void interleave_kernel(
    const float* __restrict__ Wq, const float* __restrict__ Wk,
    const float* __restrict__ Wv, const float* __restrict__ Wo,
    const float* __restrict__ W1, const float* __restrict__ W2)
{
    int m = blockIdx.y;
    const float* W; float2* O; int C, tot;
    switch (m) {
        case 0: W = Wq; O = g_Wqi; C = D;   tot = 64 * D;   break;
        case 1: W = Wk; O = g_Wki; C = D;   tot = 64 * D;   break;
        case 2: W = Wv; O = g_Wvi; C = D;   tot = 64 * D;   break;
        case 3: W = Wo; O = g_Woi; C = D;   tot = 64 * D;   break;
        case 4: W = W1; O = g_W1i; C = DFF; tot = 64 * DFF; break;
        default:W = W2; O = g_W2i; C = D;   tot = 128 * D;  break;
    }
    int idx = blockIdx.x * 256 + threadIdx.x;
    if (idx >= tot) return;
    int k2 = idx / C, c = idx % C;
    O[idx] = make_float2(W[(2 * k2) * C + c], W[(2 * k2 + 1) * C + c]);
}

// ---------------- zero in-degree counters ----------------------------------
__global__ void zero_cnt_kernel() {
    int i = blockIdx.x * blockDim.x + threadIdx.x;
    if (i < N_NODES) g_cnt[i] = 0;
}

// ---------------- bucket edges by dst --------------------------------------
__global__ __launch_bounds__(256) void scatter_kernel(
    const int* __restrict__ src, const int* __restrict__ dst)
{
    int e = blockIdx.x * 256 + threadIdx.x;
    if (e >= N_EDGES) return;
    int d = dst[e];
    int pos = atomicAdd(&g_cnt[d], 1);
    if (pos < CAP) g_csr[(long)d * CAP + pos] = src[e];
}

// ---------------- QKV projection with k-packed FFMA2 -----------------------
// grid = (3125, 3). 256 threads, 32-node tile (100000 = 32*3125, no tail).
// Thread: 8 nodes x 2 cols; acc packed over (k even, k odd).
__global__ __launch_bounds__(256, 4) void qkv_kernel(const float* __restrict__ h)
{
    __shared__ float hs[32 * D];
    int t = threadIdx.x;
    int n0 = blockIdx.x * 32;
    int wsel = blockIdx.y;

    // load h tile: warp w loads node rows w, w+8, w+16, w+24 (coalesced)
    {
        int w = t >> 5, lane = t & 31;
#pragma unroll
        for (int j = 0; j < 4; j++) {
            int n = w + j * 8;
            float4 v = ((const float4*)h)[(long)(n0 + n) * (D / 4) + lane];
            *(float4*)&hs[n * D + lane * 4] = v;
        }
    }
    __syncthreads();

    const u64* __restrict__ Wi = (const u64*)((wsel == 0) ? g_Wqi
                                : (wsel == 1) ? g_Wki : g_Wvi);

    int col2 = (t & 63) * 2;          // cols col2, col2+1
    int nb   = (t >> 6) * 8;          // 8 nodes

    u64 acc2[8][2];
#pragma unroll
    for (int i = 0; i < 8; i++) { acc2[i][0] = 0ull; acc2[i][1] = 0ull; }

#pragma unroll 4
    for (int k2 = 0; k2 < 64; k2++) {
        ulonglong2 wp = *(const ulonglong2*)&Wi[k2 * D + col2];
#pragma unroll
        for (int i = 0; i < 8; i++) {
            u64 hp = *(const u64*)&hs[(nb + i) * D + k2 * 2];
            acc2[i][0] = ffma2(hp, wp.x, acc2[i][0]);
            acc2[i][1] = ffma2(hp, wp.y, acc2[i][1]);
        }
    }

    float* O = (wsel == 0) ? g_Q : (wsel == 1) ? g_KV : g_KV + D;
    long rowstride = (wsel == 0) ? D : 2 * D;
#pragma unroll
    for (int i = 0; i < 8; i++) {
        int n = n0 + nb + i;
        float2 r = make_float2(hsum2(acc2[i][0]), hsum2(acc2[i][1]));
        *(float2*)&O[(long)n * rowstride + col2] = r;
    }
}

// ---------------- aggregation: one warp per dst node -----------------------
// 2-edge-deep software pipeline (4 concurrent 128B gathers in flight).
__global__ __launch_bounds__(256) void agg_kernel()
{
    int n = blockIdx.x * 8 + (threadIdx.x >> 5);
    int lane = threadIdx.x & 31;

    float4 q = *(const float4*)&g_Q[(long)n * D + lane * 4];
    float4 acc = make_float4(0.f, 0.f, 0.f, 0.f);
    float accz = 0.f;

    int deg = g_cnt[n];
    if (deg > CAP) deg = CAP;
    const int* __restrict__ lst = &g_csr[(long)n * CAP];

    float4 kA, vA, kB, vB;
    if (deg > 0) {
        int s = __ldg(&lst[0]);
        kA = __ldg((const float4*)&g_KV[(long)s * 2 * D + lane * 4]);
        vA = __ldg((const float4*)&g_KV[(long)s * 2 * D + D + lane * 4]);
    }
    if (deg > 1) {
        int s = __ldg(&lst[1]);
        kB = __ldg((const float4*)&g_KV[(long)s * 2 * D + lane * 4]);
        vB = __ldg((const float4*)&g_KV[(long)s * 2 * D + D + lane * 4]);
    }

    for (int j = 0; j < deg; j += 2) {
        float4 k0 = kA, v0 = vA, k1 = kB, v1 = vB;
        if (j + 2 < deg) {
            int s = __ldg(&lst[j + 2]);
            kA = __ldg((const float4*)&g_KV[(long)s * 2 * D + lane * 4]);
            vA = __ldg((const float4*)&g_KV[(long)s * 2 * D + D + lane * 4]);
        }
        if (j + 3 < deg) {
            int s = __ldg(&lst[j + 3]);
            kB = __ldg((const float4*)&g_KV[(long)s * 2 * D + lane * 4]);
            vB = __ldg((const float4*)&g_KV[(long)s * 2 * D + D + lane * 4]);
        }
        {
            float ps = k0.x * q.x + k0.y * q.y + k0.z * q.z + k0.w * q.w;
            ps += __shfl_xor_sync(0xffffffff, ps, 1);
            ps += __shfl_xor_sync(0xffffffff, ps, 2);
            float sc = __expf(fminf(fmaxf(ps * 0.25f, -5.f), 5.f));
            acc.x += sc * v0.x; acc.y += sc * v0.y;
            acc.z += sc * v0.z; acc.w += sc * v0.w;
            accz += sc;
        }
        if (j + 1 < deg) {
            float ps = k1.x * q.x + k1.y * q.y + k1.z * q.z + k1.w * q.w;
            ps += __shfl_xor_sync(0xffffffff, ps, 1);
            ps += __shfl_xor_sync(0xffffffff, ps, 2);
            float sc = __expf(fminf(fmaxf(ps * 0.25f, -5.f), 5.f));
            acc.x += sc * v1.x; acc.y += sc * v1.y;
            acc.z += sc * v1.z; acc.w += sc * v1.w;
            accz += sc;
        }
    }

    *(float4*)&g_wV[(long)n * D + lane * 4] = acc;
    if ((lane & 3) == 0) g_z[(long)n * H + (lane >> 2)] = accz;
}

// ---------------- epilogue: attn-norm + Wo + LN1 + FFN + LN2 ---------------
__device__ __forceinline__ void warp_ln4(float* buf, const float* __restrict__ g,
                                         const float* __restrict__ b,
                                         float* outbase, int t)
{
    int w = t >> 5, lane = t & 31;
    float4 gv = *(const float4*)&g[lane * 4];
    float4 bv = *(const float4*)&b[lane * 4];
#pragma unroll
    for (int i = 0; i < 4; i++) {
        int n = w * 4 + i;
        float4 v = *(float4*)&buf[n * D + lane * 4];
        float s  = v.x + v.y + v.z + v.w;
        float sq = v.x * v.x + v.y * v.y + v.z * v.z + v.w * v.w;
#pragma unroll
        for (int off = 16; off >= 1; off >>= 1) {
            s  += __shfl_xor_sync(0xffffffff, s, off);
            sq += __shfl_xor_sync(0xffffffff, sq, off);
        }
        float mu  = s * (1.f / D);
        float var = sq * (1.f / D) - mu * mu;
        float rs  = rsqrtf(var + 1e-5f);
        float4 o;
        o.x = (v.x - mu) * rs * gv.x + bv.x;
        o.y = (v.y - mu) * rs * gv.y + bv.y;
        o.z = (v.z - mu) * rs * gv.z + bv.z;
        o.w = (v.w - mu) * rs * gv.w + bv.w;
        *(float4*)&outbase[n * D + lane * 4] = o;
    }
}

__global__ __launch_bounds__(256) void epi_kernel(
    const float* __restrict__ h,
    const float* __restrict__ bo,
    const float* __restrict__ ln1g, const float* __restrict__ ln1b,
    const float* __restrict__ b1,
    const float* __restrict__ b2,
    const float* __restrict__ ln2g, const float* __restrict__ ln2b,
    float* __restrict__ out)
{
    __shared__ float sm[12288];           // 48KB
    float* XS = sm;                       // [32][128]
    float* A  = sm + 4096;                // [32][128]; later reused as FS
    float* FS = sm + 4096;                // [32][256]

    int t = threadIdx.x;
    int n0 = blockIdx.x * 32;

    // step 1: h_attn = wV / (z + eps)
    {
        int nl = t >> 3;
        int head = t & 7;
        int gn = n0 + nl;
        float inv = 1.f / (g_z[(long)gn * H + head] + 1e-6f);
        const float4* s4 = (const float4*)&g_wV[(long)gn * D + head * 16];
        float4* a4 = (float4*)&A[nl * D + head * 16];
#pragma unroll
        for (int j = 0; j < 4; j++) {
            float4 v = s4[j];
            v.x *= inv; v.y *= inv; v.z *= inv; v.w *= inv;
            a4[j] = v;
        }
    }
    __syncthreads();

    int col2 = (t & 63) * 2;
    int nb   = (t >> 6) * 8;

    // step 2: XS = h + A @ Wo + bo   (k-packed)
    {
        const u64* __restrict__ Wi = (const u64*)g_Woi;
        u64 acc2[8][2];
#pragma unroll
        for (int i = 0; i < 8; i++) { acc2[i][0] = 0ull; acc2[i][1] = 0ull; }
#pragma unroll 4
        for (int k2 = 0; k2 < 64; k2++) {
            ulonglong2 wp = *(const ulonglong2*)&Wi[k2 * D + col2];
#pragma unroll
            for (int i = 0; i < 8; i++) {
                u64 hp = *(const u64*)&A[(nb + i) * D + k2 * 2];
                acc2[i][0] = ffma2(hp, wp.x, acc2[i][0]);
                acc2[i][1] = ffma2(hp, wp.y, acc2[i][1]);
            }
        }
        float2 bov = *(const float2*)&bo[col2];
        __syncthreads();   // all A reads done before XS writes (disjoint, but keep order)
#pragma unroll
        for (int i = 0; i < 8; i++) {
            float2 hv = *(const float2*)&h[(long)(n0 + nb + i) * D + col2];
            float2 x;
            x.x = hv.x + hsum2(acc2[i][0]) + bov.x;
            x.y = hv.y + hsum2(acc2[i][1]) + bov.y;
            *(float2*)&XS[(nb + i) * D + col2] = x;
        }
    }
    __syncthreads();

    // step 3: LN1 in place on XS
    warp_ln4(XS, ln1g, ln1b, XS, t);
    __syncthreads();

    // step 4: FS = relu(XS @ W1 + b1), two column halves
    {
        const u64* __restrict__ Wi = (const u64*)g_W1i;
#pragma unroll
        for (int cc = 0; cc < DFF; cc += 128) {
            int c2 = cc + col2;
            u64 acc2[8][2];
#pragma unroll
            for (int i = 0; i < 8; i++) { acc2[i][0] = 0ull; acc2[i][1] = 0ull; }
#pragma unroll 4
            for (int k2 = 0; k2 < 64; k2++) {
                ulonglong2 wp = *(const ulonglong2*)&Wi[k2 * DFF + c2];
#pragma unroll
                for (int i = 0; i < 8; i++) {
                    u64 hp = *(const u64*)&XS[(nb + i) * D + k2 * 2];
                    acc2[i][0] = ffma2(hp, wp.x, acc2[i][0]);
                    acc2[i][1] = ffma2(hp, wp.y, acc2[i][1]);
                }
            }
            float2 b1v = *(const float2*)&b1[c2];
            if (cc == 0) __syncthreads();   // XS reads done before FS (=A) writes
#pragma unroll
            for (int i = 0; i < 8; i++) {
                float2 f;
                f.x = fmaxf(hsum2(acc2[i][0]) + b1v.x, 0.f);
                f.y = fmaxf(hsum2(acc2[i][1]) + b1v.y, 0.f);
                *(float2*)&FS[(nb + i) * DFF + c2] = f;
            }
        }
    }
    __syncthreads();

    // step 5: pre-LN2 = XS + FS @ W2 + b2   (k-packed over 256)
    {
        const u64* __restrict__ Wi = (const u64*)g_W2i;
        u64 acc2[8][2];
#pragma unroll
        for (int i = 0; i < 8; i++) { acc2[i][0] = 0ull; acc2[i][1] = 0ull; }
#pragma unroll 4
        for (int k2 = 0; k2 < 128; k2++) {
            ulonglong2 wp = *(const ulonglong2*)&Wi[k2 * D + col2];
#pragma unroll
            for (int i = 0; i < 8; i++) {
                u64 hp = *(const u64*)&FS[(nb + i) * DFF + k2 * 2];
                acc2[i][0] = ffma2(hp, wp.x, acc2[i][0]);
                acc2[i][1] = ffma2(hp, wp.y, acc2[i][1]);
            }
        }
        __syncthreads();   // all FS reads done before overwriting XS region? (disjoint) keep order
        float2 b2v = *(const float2*)&b2[col2];
#pragma unroll
        for (int i = 0; i < 8; i++) {
            float2 x = *(float2*)&XS[(nb + i) * D + col2];
            x.x += hsum2(acc2[i][0]) + b2v.x;
            x.y += hsum2(acc2[i][1]) + b2v.y;
            *(float2*)&XS[(nb + i) * D + col2] = x;
        }
    }
    __syncthreads();

    // step 6: LN2 -> global out
    warp_ln4(XS, ln2g, ln2b, out + (long)n0 * D, t);
}

// ---------------- launch ----------------------------------------------------
extern "C" void kernel_launch(void* const* d_in, const int* in_sizes, int n_in,
                              void* d_out, int out_size)
{
    const float* h    = (const float*)d_in[0];
    const int*   src  = (const int*)  d_in[1];
    const int*   dst  = (const int*)  d_in[2];
    const float* Wq   = (const float*)d_in[3];
    const float* Wk   = (const float*)d_in[4];
    const float* Wv   = (const float*)d_in[5];
    const float* Wo   = (const float*)d_in[6];
    const float* bo   = (const float*)d_in[7];
    const float* ln1g = (const float*)d_in[8];
    const float* ln1b = (const float*)d_in[9];
    const float* W1   = (const float*)d_in[10];
    const float* b1   = (const float*)d_in[11];
    const float* W2   = (const float*)d_in[12];
    const float* b2   = (const float*)d_in[13];
    const float* ln2g = (const float*)d_in[14];
    const float* ln2b = (const float*)d_in[15];
    float* out = (float*)d_out;

    dim3 igrid(64, 6);
    interleave_kernel<<<igrid, 256>>>(Wq, Wk, Wv, Wo, W1, W2);
    zero_cnt_kernel<<<(N_NODES + 255) / 256, 256>>>();
    scatter_kernel<<<N_EDGES / 256, 256>>>(src, dst);
    dim3 qgrid(N_NODES / 32, 3);
    qkv_kernel<<<qgrid, 256>>>(h);
    agg_kernel<<<N_NODES / 8, 256>>>();
    epi_kernel<<<N_NODES / 32, 256>>>(h, bo, ln1g, ln1b,
                                      b1, b2, ln2g, ln2b, out);
}